// round 6
// baseline (speedup 1.0000x reference)
#include <cuda_runtime.h>
#include <cuda_bf16.h>
#include <cstdint>

// Problem constants (fixed by the dataset)
#define NN 100000
#define EE 3200000
#define F0 256
#define HID 128
#define NCLS 64

// ---------------- scratch (static device globals; no allocation) ------------
// Referenced ONLY from device code: no cudaGetSymbolAddress / host symbol APIs.
__device__ float g_bufA[(size_t)NN * HID];   // 51.2 MB  (GEMM output)
__device__ float g_bufB[(size_t)NN * HID];   // 51.2 MB  (aggregation output)
__device__ int   g_csr[EE];                  // 12.8 MB
__device__ int   g_deg_in[NN];
__device__ int   g_deg_out[NN];
__device__ float g_nsrc[NN];
__device__ float g_ndst[NN];
__device__ int   g_rowptr[NN + 1];
__device__ int   g_wptr[NN];
__device__ int   g_incl[NN];
__device__ int   g_bsums[256];

// ---------------- graph preprocessing ---------------------------------------
__global__ void k_zero_deg() {
    int i = blockIdx.x * blockDim.x + threadIdx.x;
    if (i < NN) { g_deg_in[i] = 0; g_deg_out[i] = 0; }
}

// NOTE: src/dst are int32 (JAX x64 is disabled; astype(int64) is a no-op there).
__global__ void k_count(const int* __restrict__ src,
                        const int* __restrict__ dst) {
    int e = blockIdx.x * blockDim.x + threadIdx.x;
    if (e < EE) {
        atomicAdd(&g_deg_out[src[e]], 1);
        atomicAdd(&g_deg_in[dst[e]], 1);
    }
}

__global__ void k_norms() {
    int i = blockIdx.x * blockDim.x + threadIdx.x;
    if (i < NN) {
        int d_o = g_deg_out[i];
        int d_i = g_deg_in[i];
        g_nsrc[i] = rsqrtf((float)(d_o > 0 ? d_o : 1));
        g_ndst[i] = rsqrtf((float)(d_i > 0 ? d_i : 1));
    }
}

// Scan phase 1: each block handles 1024 elements (256 threads x 4), writes
// block-local inclusive scan to g_incl and block total to g_bsums.
__global__ void k_scan1() {
    __shared__ int sh[256];
    const int tid = threadIdx.x;
    const int base = blockIdx.x * 1024 + tid * 4;
    int v0 = (base + 0 < NN) ? g_deg_in[base + 0] : 0;
    int v1 = (base + 1 < NN) ? g_deg_in[base + 1] : 0;
    int v2 = (base + 2 < NN) ? g_deg_in[base + 2] : 0;
    int v3 = (base + 3 < NN) ? g_deg_in[base + 3] : 0;
    int p0 = v0, p1 = p0 + v1, p2 = p1 + v2, p3 = p2 + v3;
    sh[tid] = p3;
    __syncthreads();
    for (int off = 1; off < 256; off <<= 1) {
        int t = (tid >= off) ? sh[tid - off] : 0;
        __syncthreads();
        sh[tid] += t;
        __syncthreads();
    }
    int toff = sh[tid] - p3;   // exclusive offset of this thread's chunk
    if (base + 0 < NN) g_incl[base + 0] = toff + p0;
    if (base + 1 < NN) g_incl[base + 1] = toff + p1;
    if (base + 2 < NN) g_incl[base + 2] = toff + p2;
    if (base + 3 < NN) g_incl[base + 3] = toff + p3;
    if (tid == 0) g_bsums[blockIdx.x] = sh[255];
}

// Scan phase 2: single block scans the (<=128) block sums inclusively.
__global__ void k_scan2(int nb) {
    __shared__ int sh[128];
    const int tid = threadIdx.x;
    sh[tid] = (tid < nb) ? g_bsums[tid] : 0;
    __syncthreads();
    for (int off = 1; off < 128; off <<= 1) {
        int t = (tid >= off) ? sh[tid - off] : 0;
        __syncthreads();
        sh[tid] += t;
        __syncthreads();
    }
    if (tid < nb) g_bsums[tid] = sh[tid];
}

// Scan phase 3: produce exclusive row_ptr (+ copy to write pointers).
__global__ void k_scan3() {
    int i = blockIdx.x * blockDim.x + threadIdx.x;
    if (i < NN) {
        int blk = i >> 10;
        int off = (blk > 0) ? g_bsums[blk - 1] : 0;
        int excl = off + g_incl[i] - g_deg_in[i];
        g_rowptr[i] = excl;
        g_wptr[i] = excl;
    }
    if (i == 0) g_rowptr[NN] = EE;
}

__global__ void k_scatter(const int* __restrict__ src,
                          const int* __restrict__ dst) {
    int e = blockIdx.x * blockDim.x + threadIdx.x;
    if (e < EE) {
        int d = dst[e];
        int pos = atomicAdd(&g_wptr[d], 1);
        g_csr[pos] = src[e];
    }
}

// ---------------- dense GEMM: g_bufA[M,NC] = A[M,K] @ B[K,NC] ---------------
// BM=128, BN=64, BK=16, TM=8, TN=4, 256 threads.
// FROM_X selects the external input x (layer 0) vs internal g_bufB.
template<bool FROM_X>
__global__ void k_gemm(const float* __restrict__ xext,
                       const float* __restrict__ B,
                       int M, int K, int NC) {
    const float* __restrict__ A = FROM_X ? xext : (const float*)g_bufB;
    float* __restrict__ C = g_bufA;

    __shared__ float As[16][132];   // [k][m], padded (132 % 32 == 4)
    __shared__ float Bs[16][64];    // [k][n]
    const int tid = threadIdx.x;
    const int tx = tid & 15;        // 0..15 -> 64 cols
    const int ty = tid >> 4;        // 0..15 -> 128 rows
    const int rowBase = blockIdx.x * 128;
    const int colBase = blockIdx.y * 64;

    float acc[8][4];
#pragma unroll
    for (int m = 0; m < 8; m++)
#pragma unroll
        for (int n = 0; n < 4; n++) acc[m][n] = 0.f;

    const int arow = tid >> 2;          // 0..63
    const int acol = (tid & 3) * 4;     // 0,4,8,12
    const int brow = tid >> 4;          // 0..15
    const int bcol = (tid & 15) * 4;    // 0..60

    for (int k0 = 0; k0 < K; k0 += 16) {
#pragma unroll
        for (int p = 0; p < 2; p++) {
            int r = arow + p * 64;
            int grow = rowBase + r;
            float4 a = (grow < M)
                ? *(const float4*)&A[(size_t)grow * K + k0 + acol]
                : make_float4(0.f, 0.f, 0.f, 0.f);
            As[acol + 0][r] = a.x;
            As[acol + 1][r] = a.y;
            As[acol + 2][r] = a.z;
            As[acol + 3][r] = a.w;
        }
        {
            float4 b = *(const float4*)&B[(size_t)(k0 + brow) * NC + colBase + bcol];
            *(float4*)&Bs[brow][bcol] = b;
        }
        __syncthreads();
#pragma unroll
        for (int k = 0; k < 16; k++) {
            float4 a0 = *(const float4*)&As[k][ty * 8];
            float4 a1 = *(const float4*)&As[k][ty * 8 + 4];
            float4 bv = *(const float4*)&Bs[k][tx * 4];
            float am[8] = {a0.x, a0.y, a0.z, a0.w, a1.x, a1.y, a1.z, a1.w};
            float bn[4] = {bv.x, bv.y, bv.z, bv.w};
#pragma unroll
            for (int m = 0; m < 8; m++)
#pragma unroll
                for (int n = 0; n < 4; n++)
                    acc[m][n] += am[m] * bn[n];
        }
        __syncthreads();
    }
#pragma unroll
    for (int m = 0; m < 8; m++) {
        int grow = rowBase + ty * 8 + m;
        if (grow < M) {
            float4 o = make_float4(acc[m][0], acc[m][1], acc[m][2], acc[m][3]);
            *(float4*)&C[(size_t)grow * NC + colBase + tx * 4] = o;
        }
    }
}

// ---------------- aggregation: bufB[n] = n_dst[n]*sum(n_src[c]*bufA[c]) + b -
// One warp per node, 128 features -> float4 per lane.
__global__ void k_agg128(const float* __restrict__ bias) {
    const float* __restrict__ hin = (const float*)g_bufA;
    float* __restrict__ hout = g_bufB;
    int gt = blockIdx.x * blockDim.x + threadIdx.x;
    int node = gt >> 5;
    int lane = gt & 31;
    if (node >= NN) return;
    int s0 = g_rowptr[node], s1 = g_rowptr[node + 1];
    float4 acc0 = make_float4(0.f, 0.f, 0.f, 0.f);
    float4 acc1 = make_float4(0.f, 0.f, 0.f, 0.f);
    int e = s0;
    for (; e + 1 < s1; e += 2) {
        int c0 = g_csr[e];
        int c1 = g_csr[e + 1];
        float ns0 = g_nsrc[c0];
        float ns1 = g_nsrc[c1];
        float4 v0 = *(const float4*)&hin[(size_t)c0 * 128 + lane * 4];
        float4 v1 = *(const float4*)&hin[(size_t)c1 * 128 + lane * 4];
        acc0.x += ns0 * v0.x; acc0.y += ns0 * v0.y;
        acc0.z += ns0 * v0.z; acc0.w += ns0 * v0.w;
        acc1.x += ns1 * v1.x; acc1.y += ns1 * v1.y;
        acc1.z += ns1 * v1.z; acc1.w += ns1 * v1.w;
    }
    if (e < s1) {
        int c0 = g_csr[e];
        float ns0 = g_nsrc[c0];
        float4 v0 = *(const float4*)&hin[(size_t)c0 * 128 + lane * 4];
        acc0.x += ns0 * v0.x; acc0.y += ns0 * v0.y;
        acc0.z += ns0 * v0.z; acc0.w += ns0 * v0.w;
    }
    float nd = g_ndst[node];
    float4 bb = *(const float4*)&bias[lane * 4];
    float4 o;
    o.x = (acc0.x + acc1.x) * nd + bb.x;
    o.y = (acc0.y + acc1.y) * nd + bb.y;
    o.z = (acc0.z + acc1.z) * nd + bb.z;
    o.w = (acc0.w + acc1.w) * nd + bb.w;
    *(float4*)&hout[(size_t)node * 128 + lane * 4] = o;
}

// Final layer: 64 feats per node + bias + row softmax, fused. float2 per lane.
__global__ void k_agg64_softmax(float* __restrict__ out,
                                const float* __restrict__ bias) {
    const float* __restrict__ hin = (const float*)g_bufA;
    int gt = blockIdx.x * blockDim.x + threadIdx.x;
    int node = gt >> 5;
    int lane = gt & 31;
    if (node >= NN) return;
    int s0 = g_rowptr[node], s1 = g_rowptr[node + 1];
    float2 acc0 = make_float2(0.f, 0.f);
    float2 acc1 = make_float2(0.f, 0.f);
    int e = s0;
    for (; e + 1 < s1; e += 2) {
        int c0 = g_csr[e];
        int c1 = g_csr[e + 1];
        float ns0 = g_nsrc[c0];
        float ns1 = g_nsrc[c1];
        float2 v0 = *(const float2*)&hin[(size_t)c0 * 64 + lane * 2];
        float2 v1 = *(const float2*)&hin[(size_t)c1 * 64 + lane * 2];
        acc0.x += ns0 * v0.x; acc0.y += ns0 * v0.y;
        acc1.x += ns1 * v1.x; acc1.y += ns1 * v1.y;
    }
    if (e < s1) {
        int c0 = g_csr[e];
        float ns0 = g_nsrc[c0];
        float2 v0 = *(const float2*)&hin[(size_t)c0 * 64 + lane * 2];
        acc0.x += ns0 * v0.x; acc0.y += ns0 * v0.y;
    }
    float nd = g_ndst[node];
    float bx = bias[lane * 2 + 0];
    float by = bias[lane * 2 + 1];
    float vx = (acc0.x + acc1.x) * nd + bx;
    float vy = (acc0.y + acc1.y) * nd + by;
    // warp softmax over 64 values (2 per lane)
    float m = fmaxf(vx, vy);
#pragma unroll
    for (int off = 16; off > 0; off >>= 1)
        m = fmaxf(m, __shfl_xor_sync(0xFFFFFFFFu, m, off));
    float ex = __expf(vx - m);
    float ey = __expf(vy - m);
    float s = ex + ey;
#pragma unroll
    for (int off = 16; off > 0; off >>= 1)
        s += __shfl_xor_sync(0xFFFFFFFFu, s, off);
    float inv = 1.0f / s;
    float2 o = make_float2(ex * inv, ey * inv);
    *(float2*)&out[(size_t)node * 64 + lane * 2] = o;
}

// ---------------- launch -----------------------------------------------------
// Kernel launches ONLY — no other CUDA host APIs (graph-capture safe).
extern "C" void kernel_launch(void* const* d_in, const int* in_sizes, int n_in,
                              void* d_out, int out_size) {
    const float* x   = (const float*)d_in[0];
    const int*   src = (const int*)d_in[1];    // int32: JAX x64 disabled
    const int*   dst = (const int*)d_in[2];    // int32: JAX x64 disabled
    const float* W0  = (const float*)d_in[3];
    const float* b0  = (const float*)d_in[4];
    const float* W1  = (const float*)d_in[5];
    const float* b1  = (const float*)d_in[6];
    const float* W2  = (const float*)d_in[7];
    const float* b2  = (const float*)d_in[8];
    float* out = (float*)d_out;

    const int nblk  = (NN + 255) / 256;
    const int eblk  = (EE + 255) / 256;
    const int sblk  = (NN + 1023) / 1024;   // 98

    // graph preprocessing
    k_zero_deg<<<nblk, 256>>>();
    k_count<<<eblk, 256>>>(src, dst);
    k_norms<<<nblk, 256>>>();
    k_scan1<<<sblk, 256>>>();
    k_scan2<<<1, 128>>>(sblk);
    k_scan3<<<nblk, 256>>>();
    k_scatter<<<eblk, 256>>>(src, dst);

    const int aggblk = (NN * 32 + 255) / 256;   // 12500

    // layer 0: x @ W0 -> bufA ; aggregate -> bufB
    {
        dim3 grid((NN + 127) / 128, HID / 64);
        k_gemm<true><<<grid, 256>>>(x, W0, NN, F0, HID);
        k_agg128<<<aggblk, 256>>>(b0);
    }
    // layer 1: bufB @ W1 -> bufA ; aggregate -> bufB
    {
        dim3 grid((NN + 127) / 128, HID / 64);
        k_gemm<false><<<grid, 256>>>(nullptr, W1, NN, HID, HID);
        k_agg128<<<aggblk, 256>>>(b1);
    }
    // layer 2: bufB @ W2 -> bufA ; aggregate + softmax -> out
    {
        dim3 grid((NN + 127) / 128, NCLS / 64);
        k_gemm<false><<<grid, 256>>>(nullptr, W2, NN, HID, NCLS);
        k_agg64_softmax<<<aggblk, 256>>>(out, b2);
    }
}

// round 7
// speedup vs baseline: 1.0597x; 1.0597x over previous
#include <cuda_runtime.h>
#include <cuda_bf16.h>
#include <cstdint>

// Problem constants (fixed by the dataset)
#define NN 100000
#define EE 3200000
#define F0 256
#define HID 128
#define NCLS 64

// ---------------- scratch (static device globals; no allocation) ------------
__device__ float g_bufA[(size_t)NN * HID];   // 51.2 MB  (GEMM output)
__device__ float g_bufB[(size_t)NN * HID];   // 51.2 MB  (aggregation output)
__device__ int   g_csr[EE];                  // 12.8 MB
__device__ int   g_deg_in[NN];
__device__ int   g_deg_out[NN];
__device__ float g_nsrc[NN];
__device__ float g_ndst[NN];
__device__ int   g_rowptr[NN + 1];
__device__ int   g_wptr[NN];
__device__ int   g_incl[NN];
__device__ int   g_bsums[256];

// ---------------- graph preprocessing ---------------------------------------
__global__ void k_zero_deg() {
    int i = blockIdx.x * blockDim.x + threadIdx.x;
    if (i < NN) { g_deg_in[i] = 0; g_deg_out[i] = 0; }
}

// src/dst are int32 (JAX x64 disabled; astype(int64) is a no-op there).
__global__ void k_count(const int* __restrict__ src,
                        const int* __restrict__ dst) {
    int e = blockIdx.x * blockDim.x + threadIdx.x;
    if (e < EE) {
        atomicAdd(&g_deg_out[src[e]], 1);
        atomicAdd(&g_deg_in[dst[e]], 1);
    }
}

__global__ void k_norms() {
    int i = blockIdx.x * blockDim.x + threadIdx.x;
    if (i < NN) {
        int d_o = g_deg_out[i];
        int d_i = g_deg_in[i];
        g_nsrc[i] = rsqrtf((float)(d_o > 0 ? d_o : 1));
        g_ndst[i] = rsqrtf((float)(d_i > 0 ? d_i : 1));
    }
}

__global__ void k_scan1() {
    __shared__ int sh[256];
    const int tid = threadIdx.x;
    const int base = blockIdx.x * 1024 + tid * 4;
    int v0 = (base + 0 < NN) ? g_deg_in[base + 0] : 0;
    int v1 = (base + 1 < NN) ? g_deg_in[base + 1] : 0;
    int v2 = (base + 2 < NN) ? g_deg_in[base + 2] : 0;
    int v3 = (base + 3 < NN) ? g_deg_in[base + 3] : 0;
    int p0 = v0, p1 = p0 + v1, p2 = p1 + v2, p3 = p2 + v3;
    sh[tid] = p3;
    __syncthreads();
    for (int off = 1; off < 256; off <<= 1) {
        int t = (tid >= off) ? sh[tid - off] : 0;
        __syncthreads();
        sh[tid] += t;
        __syncthreads();
    }
    int toff = sh[tid] - p3;
    if (base + 0 < NN) g_incl[base + 0] = toff + p0;
    if (base + 1 < NN) g_incl[base + 1] = toff + p1;
    if (base + 2 < NN) g_incl[base + 2] = toff + p2;
    if (base + 3 < NN) g_incl[base + 3] = toff + p3;
    if (tid == 0) g_bsums[blockIdx.x] = sh[255];
}

__global__ void k_scan2(int nb) {
    __shared__ int sh[128];
    const int tid = threadIdx.x;
    sh[tid] = (tid < nb) ? g_bsums[tid] : 0;
    __syncthreads();
    for (int off = 1; off < 128; off <<= 1) {
        int t = (tid >= off) ? sh[tid - off] : 0;
        __syncthreads();
        sh[tid] += t;
        __syncthreads();
    }
    if (tid < nb) g_bsums[tid] = sh[tid];
}

__global__ void k_scan3() {
    int i = blockIdx.x * blockDim.x + threadIdx.x;
    if (i < NN) {
        int blk = i >> 10;
        int off = (blk > 0) ? g_bsums[blk - 1] : 0;
        int excl = off + g_incl[i] - g_deg_in[i];
        g_rowptr[i] = excl;
        g_wptr[i] = excl;
    }
    if (i == 0) g_rowptr[NN] = EE;
}

__global__ void k_scatter(const int* __restrict__ src,
                          const int* __restrict__ dst) {
    int e = blockIdx.x * blockDim.x + threadIdx.x;
    if (e < EE) {
        int d = dst[e];
        int pos = atomicAdd(&g_wptr[d], 1);
        g_csr[pos] = src[e];
    }
}

// ---------------- tensor-core GEMM (TF32): g_bufA = A @ B -------------------
// BM=128, BN=NC (128 or 64), BK=32. 256 threads = 8 warps (4 in M x 2 in N).
// mma.sync.m16n8k8.tf32, fp32 accumulate. Fragments staged via a permuted
// shared layout [plane][lane] (plane stride 33 words -> conflict-free reads).

__device__ __forceinline__ uint32_t f2tf32(float f) {
    uint32_t r;
    asm("cvt.rna.tf32.f32 %0, %1;" : "=r"(r) : "f"(f));
    return r;
}

__device__ __forceinline__ void mma_tf32(float* d, const uint32_t* a, const uint32_t* b) {
    asm volatile(
        "mma.sync.aligned.m16n8k8.row.col.f32.tf32.tf32.f32 "
        "{%0,%1,%2,%3}, {%4,%5,%6,%7}, {%8,%9}, {%0,%1,%2,%3};"
        : "+f"(d[0]), "+f"(d[1]), "+f"(d[2]), "+f"(d[3])
        : "r"(a[0]), "r"(a[1]), "r"(a[2]), "r"(a[3]), "r"(b[0]), "r"(b[1]));
}

template<bool FROM_X, int BN>
__global__ __launch_bounds__(256)
void k_gemm_tc(const float* __restrict__ xext,
               const float* __restrict__ Bsrc,
               int M, int K) {
    const float* __restrict__ A = FROM_X ? xext : (const float*)g_bufB;
    float* __restrict__ C = g_bufA;
    constexpr int NC = BN;
    constexpr int BK = 32;
    constexpr int AITER = (128 * BK) / 256;      // 16
    constexpr int BITER = (BK * BN) / 256;       // 16 or 8
    constexpr int NT = BN / 16;                  // n-tiles per warp: 8 or 4

    // planes: A -> [mt(8)][ks(4)][reg(4)] = 128; B -> [nt(BN/8)][ks(4)][reg(2)]
    __shared__ uint32_t AsU[128 * 33];
    __shared__ uint32_t BsU[(BN / 8) * 4 * 2 * 33];

    const int tid  = threadIdx.x;
    const int lane = tid & 31;
    const int w    = tid >> 5;
    const int warpM = w & 3;
    const int warpN = w >> 2;
    const int rowBase = blockIdx.x * 128;

    float acc[2][NT][4];
#pragma unroll
    for (int j = 0; j < 2; j++)
#pragma unroll
        for (int n = 0; n < NT; n++)
#pragma unroll
            for (int r = 0; r < 4; r++) acc[j][n][r] = 0.f;

    uint32_t sa[AITER];
    uint32_t sb[BITER];

    auto loadAB = [&](int k0) {
#pragma unroll
        for (int i = 0; i < AITER; i++) {
            int idx = i * 256 + tid;
            int m = idx >> 5;           // BK=32: k fastest
            int k = idx & 31;
            int grow = rowBase + m;
            float v = (grow < M) ? A[(size_t)grow * K + k0 + k] : 0.f;
            sa[i] = f2tf32(v);
        }
#pragma unroll
        for (int i = 0; i < BITER; i++) {
            int idx = i * 256 + tid;
            int k = idx / BN;           // n fastest (coalesced)
            int n = idx % BN;
            float v = Bsrc[(size_t)(k0 + k) * NC + n];
            sb[i] = f2tf32(v);
        }
    };

    auto storeAB = [&]() {
#pragma unroll
        for (int i = 0; i < AITER; i++) {
            int idx = i * 256 + tid;
            int m = idx >> 5;
            int k = idx & 31;
            int mt = m >> 4, rr = m & 15;
            int ks = k >> 3;
            int ln = ((rr & 7) << 2) | (k & 3);
            int reg = (rr >> 3) | (((k >> 2) & 1) << 1);
            int plane = ((mt << 2) | ks) * 4 + reg;
            AsU[plane * 33 + ln] = sa[i];
        }
#pragma unroll
        for (int i = 0; i < BITER; i++) {
            int idx = i * 256 + tid;
            int k = idx / BN;
            int n = idx % BN;
            int nt = n >> 3;
            int ks = k >> 3;
            int ln = ((n & 7) << 2) | (k & 3);
            int reg = (k >> 2) & 1;
            int plane = (nt * 4 + ks) * 2 + reg;
            BsU[plane * 33 + ln] = sb[i];
        }
    };

    const int nChunks = K / BK;
    loadAB(0);
    storeAB();
    __syncthreads();

    for (int c = 0; c < nChunks; c++) {
        if (c + 1 < nChunks) loadAB((c + 1) * BK);

#pragma unroll
        for (int ks = 0; ks < 4; ks++) {
            uint32_t a[2][4];
#pragma unroll
            for (int j = 0; j < 2; j++) {
                int mtp = ((warpM * 2 + j) * 4 + ks) * 4;
#pragma unroll
                for (int r = 0; r < 4; r++)
                    a[j][r] = AsU[(mtp + r) * 33 + lane];
            }
#pragma unroll
            for (int n = 0; n < NT; n++) {
                uint32_t b[2];
                int ntp = ((warpN * NT + n) * 4 + ks) * 2;
                b[0] = BsU[ntp * 33 + lane];
                b[1] = BsU[(ntp + 1) * 33 + lane];
                mma_tf32(acc[0][n], a[0], b);
                mma_tf32(acc[1][n], a[1], b);
            }
        }
        __syncthreads();
        if (c + 1 < nChunks) {
            storeAB();
            __syncthreads();
        }
    }

    // epilogue
    const int r0 = rowBase + warpM * 32;
#pragma unroll
    for (int j = 0; j < 2; j++) {
        int row = r0 + j * 16 + (lane >> 2);
#pragma unroll
        for (int n = 0; n < NT; n++) {
            int col = warpN * (NT * 8) + n * 8 + (lane & 3) * 2;
            if (row < M) {
                float2 o0 = make_float2(acc[j][n][0], acc[j][n][1]);
                *(float2*)&C[(size_t)row * NC + col] = o0;
            }
            if (row + 8 < M) {
                float2 o1 = make_float2(acc[j][n][2], acc[j][n][3]);
                *(float2*)&C[(size_t)(row + 8) * NC + col] = o1;
            }
        }
    }
}

// ---------------- aggregation: bufB[n] = n_dst[n]*sum(n_src[c]*bufA[c]) + b -
__global__ void k_agg128(const float* __restrict__ bias) {
    const float* __restrict__ hin = (const float*)g_bufA;
    float* __restrict__ hout = g_bufB;
    int gt = blockIdx.x * blockDim.x + threadIdx.x;
    int node = gt >> 5;
    int lane = gt & 31;
    if (node >= NN) return;
    int s0 = g_rowptr[node], s1 = g_rowptr[node + 1];
    float4 acc0 = make_float4(0.f, 0.f, 0.f, 0.f);
    float4 acc1 = make_float4(0.f, 0.f, 0.f, 0.f);
    int e = s0;
    for (; e + 1 < s1; e += 2) {
        int c0 = g_csr[e];
        int c1 = g_csr[e + 1];
        float ns0 = g_nsrc[c0];
        float ns1 = g_nsrc[c1];
        float4 v0 = *(const float4*)&hin[(size_t)c0 * 128 + lane * 4];
        float4 v1 = *(const float4*)&hin[(size_t)c1 * 128 + lane * 4];
        acc0.x += ns0 * v0.x; acc0.y += ns0 * v0.y;
        acc0.z += ns0 * v0.z; acc0.w += ns0 * v0.w;
        acc1.x += ns1 * v1.x; acc1.y += ns1 * v1.y;
        acc1.z += ns1 * v1.z; acc1.w += ns1 * v1.w;
    }
    if (e < s1) {
        int c0 = g_csr[e];
        float ns0 = g_nsrc[c0];
        float4 v0 = *(const float4*)&hin[(size_t)c0 * 128 + lane * 4];
        acc0.x += ns0 * v0.x; acc0.y += ns0 * v0.y;
        acc0.z += ns0 * v0.z; acc0.w += ns0 * v0.w;
    }
    float nd = g_ndst[node];
    float4 bb = *(const float4*)&bias[lane * 4];
    float4 o;
    o.x = (acc0.x + acc1.x) * nd + bb.x;
    o.y = (acc0.y + acc1.y) * nd + bb.y;
    o.z = (acc0.z + acc1.z) * nd + bb.z;
    o.w = (acc0.w + acc1.w) * nd + bb.w;
    *(float4*)&hout[(size_t)node * 128 + lane * 4] = o;
}

__global__ void k_agg64_softmax(float* __restrict__ out,
                                const float* __restrict__ bias) {
    const float* __restrict__ hin = (const float*)g_bufA;
    int gt = blockIdx.x * blockDim.x + threadIdx.x;
    int node = gt >> 5;
    int lane = gt & 31;
    if (node >= NN) return;
    int s0 = g_rowptr[node], s1 = g_rowptr[node + 1];
    float2 acc0 = make_float2(0.f, 0.f);
    float2 acc1 = make_float2(0.f, 0.f);
    int e = s0;
    for (; e + 1 < s1; e += 2) {
        int c0 = g_csr[e];
        int c1 = g_csr[e + 1];
        float ns0 = g_nsrc[c0];
        float ns1 = g_nsrc[c1];
        float2 v0 = *(const float2*)&hin[(size_t)c0 * 64 + lane * 2];
        float2 v1 = *(const float2*)&hin[(size_t)c1 * 64 + lane * 2];
        acc0.x += ns0 * v0.x; acc0.y += ns0 * v0.y;
        acc1.x += ns1 * v1.x; acc1.y += ns1 * v1.y;
    }
    if (e < s1) {
        int c0 = g_csr[e];
        float ns0 = g_nsrc[c0];
        float2 v0 = *(const float2*)&hin[(size_t)c0 * 64 + lane * 2];
        acc0.x += ns0 * v0.x; acc0.y += ns0 * v0.y;
    }
    float nd = g_ndst[node];
    float bx = bias[lane * 2 + 0];
    float by = bias[lane * 2 + 1];
    float vx = (acc0.x + acc1.x) * nd + bx;
    float vy = (acc0.y + acc1.y) * nd + by;
    float m = fmaxf(vx, vy);
#pragma unroll
    for (int off = 16; off > 0; off >>= 1)
        m = fmaxf(m, __shfl_xor_sync(0xFFFFFFFFu, m, off));
    float ex = __expf(vx - m);
    float ey = __expf(vy - m);
    float s = ex + ey;
#pragma unroll
    for (int off = 16; off > 0; off >>= 1)
        s += __shfl_xor_sync(0xFFFFFFFFu, s, off);
    float inv = 1.0f / s;
    float2 o = make_float2(ex * inv, ey * inv);
    *(float2*)&out[(size_t)node * 64 + lane * 2] = o;
}

// ---------------- launch -----------------------------------------------------
extern "C" void kernel_launch(void* const* d_in, const int* in_sizes, int n_in,
                              void* d_out, int out_size) {
    const float* x   = (const float*)d_in[0];
    const int*   src = (const int*)d_in[1];    // int32: JAX x64 disabled
    const int*   dst = (const int*)d_in[2];
    const float* W0  = (const float*)d_in[3];
    const float* b0  = (const float*)d_in[4];
    const float* W1  = (const float*)d_in[5];
    const float* b1  = (const float*)d_in[6];
    const float* W2  = (const float*)d_in[7];
    const float* b2  = (const float*)d_in[8];
    float* out = (float*)d_out;

    const int nblk = (NN + 255) / 256;
    const int eblk = (EE + 255) / 256;
    const int sblk = (NN + 1023) / 1024;   // 98

    // graph preprocessing
    k_zero_deg<<<nblk, 256>>>();
    k_count<<<eblk, 256>>>(src, dst);
    k_norms<<<nblk, 256>>>();
    k_scan1<<<sblk, 256>>>();
    k_scan2<<<1, 128>>>(sblk);
    k_scan3<<<nblk, 256>>>();
    k_scatter<<<eblk, 256>>>(src, dst);

    const int aggblk  = (NN * 32 + 255) / 256;   // 12500
    const int gemmblk = (NN + 127) / 128;        // 782

    // layer 0: x @ W0 -> bufA ; aggregate -> bufB
    k_gemm_tc<true, HID><<<gemmblk, 256>>>(x, W0, NN, F0);
    k_agg128<<<aggblk, 256>>>(b0);
    // layer 1: bufB @ W1 -> bufA ; aggregate -> bufB
    k_gemm_tc<false, HID><<<gemmblk, 256>>>(nullptr, W1, NN, HID);
    k_agg128<<<aggblk, 256>>>(b1);
    // layer 2: bufB @ W2 -> bufA ; aggregate + softmax -> out
    k_gemm_tc<false, NCLS><<<gemmblk, 256>>>(nullptr, W2, NN, HID);
    k_agg64_softmax<<<aggblk, 256>>>(out, b2);
}

// round 8
// speedup vs baseline: 1.1507x; 1.0858x over previous
#include <cuda_runtime.h>
#include <cuda_bf16.h>
#include <cstdint>

// Problem constants (fixed by the dataset)
#define NN 100000
#define EE 3200000
#define F0 256
#define HID 128
#define NCLS 64

// ---------------- scratch (static device globals; no allocation) ------------
__device__ __nv_bfloat16 g_hA16[(size_t)NN * HID];  // 25.6 MB (GEMM output)
__device__ __nv_bfloat16 g_hB16[(size_t)NN * HID];  // 25.6 MB (agg output)
__device__ int   g_csr[EE];                         // 12.8 MB
__device__ int   g_deg_in[NN];
__device__ int   g_deg_out[NN];
__device__ float g_nsrc[NN];
__device__ float g_ndst[NN];
__device__ int   g_rowptr[NN + 1];
__device__ int   g_wptr[NN];
__device__ int   g_incl[NN];
__device__ int   g_bsums[256];

// ---------------- graph preprocessing ---------------------------------------
__global__ void k_zero_deg() {
    int i = blockIdx.x * blockDim.x + threadIdx.x;
    if (i < NN) { g_deg_in[i] = 0; g_deg_out[i] = 0; }
}

// src/dst are int32 (JAX x64 disabled; astype(int64) is a no-op there).
__global__ void k_count(const int* __restrict__ src,
                        const int* __restrict__ dst) {
    int e = blockIdx.x * blockDim.x + threadIdx.x;
    if (e < EE) {
        atomicAdd(&g_deg_out[src[e]], 1);
        atomicAdd(&g_deg_in[dst[e]], 1);
    }
}

__global__ void k_norms() {
    int i = blockIdx.x * blockDim.x + threadIdx.x;
    if (i < NN) {
        int d_o = g_deg_out[i];
        int d_i = g_deg_in[i];
        g_nsrc[i] = rsqrtf((float)(d_o > 0 ? d_o : 1));
        g_ndst[i] = rsqrtf((float)(d_i > 0 ? d_i : 1));
    }
}

__global__ void k_scan1() {
    __shared__ int sh[256];
    const int tid = threadIdx.x;
    const int base = blockIdx.x * 1024 + tid * 4;
    int v0 = (base + 0 < NN) ? g_deg_in[base + 0] : 0;
    int v1 = (base + 1 < NN) ? g_deg_in[base + 1] : 0;
    int v2 = (base + 2 < NN) ? g_deg_in[base + 2] : 0;
    int v3 = (base + 3 < NN) ? g_deg_in[base + 3] : 0;
    int p0 = v0, p1 = p0 + v1, p2 = p1 + v2, p3 = p2 + v3;
    sh[tid] = p3;
    __syncthreads();
    for (int off = 1; off < 256; off <<= 1) {
        int t = (tid >= off) ? sh[tid - off] : 0;
        __syncthreads();
        sh[tid] += t;
        __syncthreads();
    }
    int toff = sh[tid] - p3;
    if (base + 0 < NN) g_incl[base + 0] = toff + p0;
    if (base + 1 < NN) g_incl[base + 1] = toff + p1;
    if (base + 2 < NN) g_incl[base + 2] = toff + p2;
    if (base + 3 < NN) g_incl[base + 3] = toff + p3;
    if (tid == 0) g_bsums[blockIdx.x] = sh[255];
}

__global__ void k_scan2(int nb) {
    __shared__ int sh[128];
    const int tid = threadIdx.x;
    sh[tid] = (tid < nb) ? g_bsums[tid] : 0;
    __syncthreads();
    for (int off = 1; off < 128; off <<= 1) {
        int t = (tid >= off) ? sh[tid - off] : 0;
        __syncthreads();
        sh[tid] += t;
        __syncthreads();
    }
    if (tid < nb) g_bsums[tid] = sh[tid];
}

__global__ void k_scan3() {
    int i = blockIdx.x * blockDim.x + threadIdx.x;
    if (i < NN) {
        int blk = i >> 10;
        int off = (blk > 0) ? g_bsums[blk - 1] : 0;
        int excl = off + g_incl[i] - g_deg_in[i];
        g_rowptr[i] = excl;
        g_wptr[i] = excl;
    }
    if (i == 0) g_rowptr[NN] = EE;
}

__global__ void k_scatter(const int* __restrict__ src,
                          const int* __restrict__ dst) {
    int e = blockIdx.x * blockDim.x + threadIdx.x;
    if (e < EE) {
        int d = dst[e];
        int pos = atomicAdd(&g_wptr[d], 1);
        g_csr[pos] = src[e];
    }
}

// ---------------- tensor-core GEMM (TF32): g_hA16 = A @ B (bf16 out) --------
// BM=128, BN=NC (128 or 64), BK=32. 256 threads = 8 warps (4 in M x 2 in N).
// mma.sync.m16n8k8.tf32, fp32 accumulate. Fragments staged via a permuted
// shared layout [plane][lane] (plane stride 33 words -> conflict-free reads).
// FROM_X: A = external fp32 x. Otherwise A = g_hB16 (bf16; exact in tf32).

__device__ __forceinline__ uint32_t f2tf32(float f) {
    uint32_t r;
    asm("cvt.rna.tf32.f32 %0, %1;" : "=r"(r) : "f"(f));
    return r;
}

__device__ __forceinline__ void mma_tf32(float* d, const uint32_t* a, const uint32_t* b) {
    asm volatile(
        "mma.sync.aligned.m16n8k8.row.col.f32.tf32.tf32.f32 "
        "{%0,%1,%2,%3}, {%4,%5,%6,%7}, {%8,%9}, {%0,%1,%2,%3};"
        : "+f"(d[0]), "+f"(d[1]), "+f"(d[2]), "+f"(d[3])
        : "r"(a[0]), "r"(a[1]), "r"(a[2]), "r"(a[3]), "r"(b[0]), "r"(b[1]));
}

template<bool FROM_X, int BN>
__global__ __launch_bounds__(256)
void k_gemm_tc(const float* __restrict__ xext,
               const float* __restrict__ Bsrc,
               int M, int K) {
    const float* __restrict__ Af = xext;                       // FROM_X
    const __nv_bfloat16* __restrict__ Ah = (const __nv_bfloat16*)g_hB16;
    __nv_bfloat16* __restrict__ C = g_hA16;
    constexpr int NC = BN;
    constexpr int BK = 32;
    constexpr int AITER = (128 * BK) / 256;      // 16 elements / thread
    constexpr int APITER = AITER / 2;            // 8 bf16x2 pairs / thread
    constexpr int BITER = (BK * BN) / 256;       // 16 or 8
    constexpr int NT = BN / 16;                  // n-tiles per warp: 8 or 4

    __shared__ uint32_t AsU[128 * 33];
    __shared__ uint32_t BsU[(BN / 8) * 4 * 2 * 33];

    const int tid  = threadIdx.x;
    const int lane = tid & 31;
    const int w    = tid >> 5;
    const int warpM = w & 3;
    const int warpN = w >> 2;
    const int rowBase = blockIdx.x * 128;

    float acc[2][NT][4];
#pragma unroll
    for (int j = 0; j < 2; j++)
#pragma unroll
        for (int n = 0; n < NT; n++)
#pragma unroll
            for (int r = 0; r < 4; r++) acc[j][n][r] = 0.f;

    uint32_t sa[AITER];     // FROM_X: tf32 elements; else first APITER hold bf16x2 pairs
    uint32_t sb[BITER];

    auto loadAB = [&](int k0) {
        if (FROM_X) {
#pragma unroll
            for (int i = 0; i < AITER; i++) {
                int idx = i * 256 + tid;
                int m = idx >> 5;           // BK=32: k fastest
                int k = idx & 31;
                int grow = rowBase + m;
                float v = (grow < M) ? Af[(size_t)grow * K + k0 + k] : 0.f;
                sa[i] = f2tf32(v);
            }
        } else {
#pragma unroll
            for (int i = 0; i < APITER; i++) {
                int pidx = i * 256 + tid;
                int m = pidx >> 4;          // 16 bf16x2 pairs per row
                int kp = pidx & 15;
                int grow = rowBase + m;
                sa[i] = (grow < M)
                    ? *(const uint32_t*)&Ah[(size_t)grow * K + k0 + kp * 2]
                    : 0u;
            }
        }
#pragma unroll
        for (int i = 0; i < BITER; i++) {
            int idx = i * 256 + tid;
            int k = idx / BN;               // n fastest (coalesced)
            int n = idx % BN;
            float v = Bsrc[(size_t)(k0 + k) * NC + n];
            sb[i] = f2tf32(v);
        }
    };

    auto storeAB = [&]() {
        if (FROM_X) {
#pragma unroll
            for (int i = 0; i < AITER; i++) {
                int idx = i * 256 + tid;
                int m = idx >> 5;
                int k = idx & 31;
                int mt = m >> 4, rr = m & 15;
                int ks = k >> 3;
                int ln = ((rr & 7) << 2) | (k & 3);
                int reg = (rr >> 3) | (((k >> 2) & 1) << 1);
                int plane = ((mt << 2) | ks) * 4 + reg;
                AsU[plane * 33 + ln] = sa[i];
            }
        } else {
#pragma unroll
            for (int i = 0; i < APITER; i++) {
                int pidx = i * 256 + tid;
                int m = pidx >> 4;
                int k = (pidx & 15) * 2;    // even
                __nv_bfloat162 p = *(__nv_bfloat162*)&sa[i];
                float2 f = __bfloat1622float2(p);
                int mt = m >> 4, rr = m & 15;
                int ks = k >> 3;
                int ln = ((rr & 7) << 2) | (k & 3);
                int reg = (rr >> 3) | (((k >> 2) & 1) << 1);
                int plane = ((mt << 2) | ks) * 4 + reg;
                // bf16 -> fp32 bits are valid tf32 (mantissa subset)
                AsU[plane * 33 + ln]     = __float_as_uint(f.x);
                AsU[plane * 33 + ln + 1] = __float_as_uint(f.y);
            }
        }
#pragma unroll
        for (int i = 0; i < BITER; i++) {
            int idx = i * 256 + tid;
            int k = idx / BN;
            int n = idx % BN;
            int nt = n >> 3;
            int ks = k >> 3;
            int ln = ((n & 7) << 2) | (k & 3);
            int reg = (k >> 2) & 1;
            int plane = (nt * 4 + ks) * 2 + reg;
            BsU[plane * 33 + ln] = sb[i];
        }
    };

    const int nChunks = K / BK;
    loadAB(0);
    storeAB();
    __syncthreads();

    for (int c = 0; c < nChunks; c++) {
        if (c + 1 < nChunks) loadAB((c + 1) * BK);

#pragma unroll
        for (int ks = 0; ks < 4; ks++) {
            uint32_t a[2][4];
#pragma unroll
            for (int j = 0; j < 2; j++) {
                int mtp = ((warpM * 2 + j) * 4 + ks) * 4;
#pragma unroll
                for (int r = 0; r < 4; r++)
                    a[j][r] = AsU[(mtp + r) * 33 + lane];
            }
#pragma unroll
            for (int n = 0; n < NT; n++) {
                uint32_t b[2];
                int ntp = ((warpN * NT + n) * 4 + ks) * 2;
                b[0] = BsU[ntp * 33 + lane];
                b[1] = BsU[(ntp + 1) * 33 + lane];
                mma_tf32(acc[0][n], a[0], b);
                mma_tf32(acc[1][n], a[1], b);
            }
        }
        __syncthreads();
        if (c + 1 < nChunks) {
            storeAB();
            __syncthreads();
        }
    }

    // epilogue: convert to bf16 pairs, store 4B per fragment half
    const int r0 = rowBase + warpM * 32;
#pragma unroll
    for (int j = 0; j < 2; j++) {
        int row = r0 + j * 16 + (lane >> 2);
#pragma unroll
        for (int n = 0; n < NT; n++) {
            int col = warpN * (NT * 8) + n * 8 + (lane & 3) * 2;
            if (row < M) {
                __nv_bfloat162 o0 = __float22bfloat162_rn(make_float2(acc[j][n][0], acc[j][n][1]));
                *(uint32_t*)&C[(size_t)row * NC + col] = *(uint32_t*)&o0;
            }
            if (row + 8 < M) {
                __nv_bfloat162 o1 = __float22bfloat162_rn(make_float2(acc[j][n][2], acc[j][n][3]));
                *(uint32_t*)&C[(size_t)(row + 8) * NC + col] = *(uint32_t*)&o1;
            }
        }
    }
}

// ---------------- aggregation (bf16 in / bf16 out) --------------------------
// hB16[n] = bf16( n_dst[n] * sum_c(n_src[c] * hA16[c]) + b )
// One warp per node; 128 feats -> 4 per lane (uint2 = 2x bf16x2); 4-edge unroll.
__global__ void k_agg128(const float* __restrict__ bias) {
    const __nv_bfloat16* __restrict__ hin = (const __nv_bfloat16*)g_hA16;
    __nv_bfloat16* __restrict__ hout = g_hB16;
    int gt = blockIdx.x * blockDim.x + threadIdx.x;
    int node = gt >> 5;
    int lane = gt & 31;
    if (node >= NN) return;
    int s0 = g_rowptr[node], s1 = g_rowptr[node + 1];
    float a0x = 0.f, a0y = 0.f, a0z = 0.f, a0w = 0.f;
    float a1x = 0.f, a1y = 0.f, a1z = 0.f, a1w = 0.f;
    float a2x = 0.f, a2y = 0.f, a2z = 0.f, a2w = 0.f;
    float a3x = 0.f, a3y = 0.f, a3z = 0.f, a3w = 0.f;
    const int fo = lane * 4;
    int e = s0;
    for (; e + 3 < s1; e += 4) {
        int c0 = g_csr[e], c1 = g_csr[e + 1], c2 = g_csr[e + 2], c3 = g_csr[e + 3];
        float n0 = g_nsrc[c0], n1 = g_nsrc[c1], n2 = g_nsrc[c2], n3 = g_nsrc[c3];
        uint2 r0 = *(const uint2*)&hin[(size_t)c0 * 128 + fo];
        uint2 r1 = *(const uint2*)&hin[(size_t)c1 * 128 + fo];
        uint2 r2 = *(const uint2*)&hin[(size_t)c2 * 128 + fo];
        uint2 r3 = *(const uint2*)&hin[(size_t)c3 * 128 + fo];
        float2 l0 = __bfloat1622float2(*(__nv_bfloat162*)&r0.x);
        float2 h0 = __bfloat1622float2(*(__nv_bfloat162*)&r0.y);
        float2 l1 = __bfloat1622float2(*(__nv_bfloat162*)&r1.x);
        float2 h1 = __bfloat1622float2(*(__nv_bfloat162*)&r1.y);
        float2 l2 = __bfloat1622float2(*(__nv_bfloat162*)&r2.x);
        float2 h2 = __bfloat1622float2(*(__nv_bfloat162*)&r2.y);
        float2 l3 = __bfloat1622float2(*(__nv_bfloat162*)&r3.x);
        float2 h3 = __bfloat1622float2(*(__nv_bfloat162*)&r3.y);
        a0x += n0 * l0.x; a0y += n0 * l0.y; a0z += n0 * h0.x; a0w += n0 * h0.y;
        a1x += n1 * l1.x; a1y += n1 * l1.y; a1z += n1 * h1.x; a1w += n1 * h1.y;
        a2x += n2 * l2.x; a2y += n2 * l2.y; a2z += n2 * h2.x; a2w += n2 * h2.y;
        a3x += n3 * l3.x; a3y += n3 * l3.y; a3z += n3 * h3.x; a3w += n3 * h3.y;
    }
    for (; e < s1; e++) {
        int c0 = g_csr[e];
        float n0 = g_nsrc[c0];
        uint2 r0 = *(const uint2*)&hin[(size_t)c0 * 128 + fo];
        float2 l0 = __bfloat1622float2(*(__nv_bfloat162*)&r0.x);
        float2 h0 = __bfloat1622float2(*(__nv_bfloat162*)&r0.y);
        a0x += n0 * l0.x; a0y += n0 * l0.y; a0z += n0 * h0.x; a0w += n0 * h0.y;
    }
    float nd = g_ndst[node];
    float4 bb = *(const float4*)&bias[fo];
    float ox = (a0x + a1x + a2x + a3x) * nd + bb.x;
    float oy = (a0y + a1y + a2y + a3y) * nd + bb.y;
    float oz = (a0z + a1z + a2z + a3z) * nd + bb.z;
    float ow = (a0w + a1w + a2w + a3w) * nd + bb.w;
    __nv_bfloat162 p0 = __float22bfloat162_rn(make_float2(ox, oy));
    __nv_bfloat162 p1 = __float22bfloat162_rn(make_float2(oz, ow));
    uint2 o;
    o.x = *(uint32_t*)&p0;
    o.y = *(uint32_t*)&p1;
    *(uint2*)&hout[(size_t)node * 128 + fo] = o;
}

// Final layer: 64 bf16 feats in, bias + softmax, fp32 out. 2 per lane.
__global__ void k_agg64_softmax(float* __restrict__ out,
                                const float* __restrict__ bias) {
    const __nv_bfloat16* __restrict__ hin = (const __nv_bfloat16*)g_hA16;
    int gt = blockIdx.x * blockDim.x + threadIdx.x;
    int node = gt >> 5;
    int lane = gt & 31;
    if (node >= NN) return;
    int s0 = g_rowptr[node], s1 = g_rowptr[node + 1];
    float a0x = 0.f, a0y = 0.f, a1x = 0.f, a1y = 0.f;
    float a2x = 0.f, a2y = 0.f, a3x = 0.f, a3y = 0.f;
    const int fo = lane * 2;
    int e = s0;
    for (; e + 3 < s1; e += 4) {
        int c0 = g_csr[e], c1 = g_csr[e + 1], c2 = g_csr[e + 2], c3 = g_csr[e + 3];
        float n0 = g_nsrc[c0], n1 = g_nsrc[c1], n2 = g_nsrc[c2], n3 = g_nsrc[c3];
        uint32_t r0 = *(const uint32_t*)&hin[(size_t)c0 * 64 + fo];
        uint32_t r1 = *(const uint32_t*)&hin[(size_t)c1 * 64 + fo];
        uint32_t r2 = *(const uint32_t*)&hin[(size_t)c2 * 64 + fo];
        uint32_t r3 = *(const uint32_t*)&hin[(size_t)c3 * 64 + fo];
        float2 v0 = __bfloat1622float2(*(__nv_bfloat162*)&r0);
        float2 v1 = __bfloat1622float2(*(__nv_bfloat162*)&r1);
        float2 v2 = __bfloat1622float2(*(__nv_bfloat162*)&r2);
        float2 v3 = __bfloat1622float2(*(__nv_bfloat162*)&r3);
        a0x += n0 * v0.x; a0y += n0 * v0.y;
        a1x += n1 * v1.x; a1y += n1 * v1.y;
        a2x += n2 * v2.x; a2y += n2 * v2.y;
        a3x += n3 * v3.x; a3y += n3 * v3.y;
    }
    for (; e < s1; e++) {
        int c0 = g_csr[e];
        float n0 = g_nsrc[c0];
        uint32_t r0 = *(const uint32_t*)&hin[(size_t)c0 * 64 + fo];
        float2 v0 = __bfloat1622float2(*(__nv_bfloat162*)&r0);
        a0x += n0 * v0.x; a0y += n0 * v0.y;
    }
    float nd = g_ndst[node];
    float vx = (a0x + a1x + a2x + a3x) * nd + bias[fo + 0];
    float vy = (a0y + a1y + a2y + a3y) * nd + bias[fo + 1];
    float m = fmaxf(vx, vy);
#pragma unroll
    for (int off = 16; off > 0; off >>= 1)
        m = fmaxf(m, __shfl_xor_sync(0xFFFFFFFFu, m, off));
    float ex = __expf(vx - m);
    float ey = __expf(vy - m);
    float s = ex + ey;
#pragma unroll
    for (int off = 16; off > 0; off >>= 1)
        s += __shfl_xor_sync(0xFFFFFFFFu, s, off);
    float inv = 1.0f / s;
    float2 o = make_float2(ex * inv, ey * inv);
    *(float2*)&out[(size_t)node * 64 + fo] = o;
}

// ---------------- launch -----------------------------------------------------
extern "C" void kernel_launch(void* const* d_in, const int* in_sizes, int n_in,
                              void* d_out, int out_size) {
    const float* x   = (const float*)d_in[0];
    const int*   src = (const int*)d_in[1];    // int32: JAX x64 disabled
    const int*   dst = (const int*)d_in[2];
    const float* W0  = (const float*)d_in[3];
    const float* b0  = (const float*)d_in[4];
    const float* W1  = (const float*)d_in[5];
    const float* b1  = (const float*)d_in[6];
    const float* W2  = (const float*)d_in[7];
    const float* b2  = (const float*)d_in[8];
    float* out = (float*)d_out;

    const int nblk = (NN + 255) / 256;
    const int eblk = (EE + 255) / 256;
    const int sblk = (NN + 1023) / 1024;   // 98

    // graph preprocessing
    k_zero_deg<<<nblk, 256>>>();
    k_count<<<eblk, 256>>>(src, dst);
    k_norms<<<nblk, 256>>>();
    k_scan1<<<sblk, 256>>>();
    k_scan2<<<1, 128>>>(sblk);
    k_scan3<<<nblk, 256>>>();
    k_scatter<<<eblk, 256>>>(src, dst);

    const int aggblk  = (NN * 32 + 255) / 256;   // 12500
    const int gemmblk = (NN + 127) / 128;        // 782

    // layer 0: x @ W0 -> hA16 ; aggregate -> hB16
    k_gemm_tc<true, HID><<<gemmblk, 256>>>(x, W0, NN, F0);
    k_agg128<<<aggblk, 256>>>(b0);
    // layer 1: hB16 @ W1 -> hA16 ; aggregate -> hB16
    k_gemm_tc<false, HID><<<gemmblk, 256>>>(nullptr, W1, NN, HID);
    k_agg128<<<aggblk, 256>>>(b1);
    // layer 2: hB16 @ W2 -> hA16 ; aggregate + softmax -> out
    k_gemm_tc<false, NCLS><<<gemmblk, 256>>>(nullptr, W2, NN, HID);
    k_agg64_softmax<<<aggblk, 256>>>(out, b2);
}

// round 10
// speedup vs baseline: 1.3867x; 1.2051x over previous
#include <cuda_runtime.h>
#include <cuda_bf16.h>
#include <cstdint>

// Problem constants (fixed by the dataset)
#define NN 100000
#define EE 3200000
#define F0 256
#define HID 128
#define NCLS 64

// ---------------- scratch (static device globals; no allocation) ------------
__device__ __nv_bfloat16 g_hA16[(size_t)NN * HID];  // 25.6 MB (GEMM output)
__device__ __nv_bfloat16 g_hB16[(size_t)NN * HID];  // 25.6 MB (agg output)
__device__ int   g_csr[EE];                         // 12.8 MB
__device__ int   g_deg_in[NN];
__device__ int   g_deg_out[NN];
__device__ float g_nsrc[NN];
__device__ float g_ndst[NN];
__device__ int   g_rowptr[NN + 1];
__device__ int   g_wptr[NN];
__device__ int   g_incl[NN];
__device__ int   g_bsums[256];

// ---------------- graph preprocessing ---------------------------------------
__global__ void k_zero_deg() {
    int i = blockIdx.x * blockDim.x + threadIdx.x;
    if (i < NN) { g_deg_in[i] = 0; g_deg_out[i] = 0; }
}

// src/dst are int32 (JAX x64 disabled; astype(int64) is a no-op there).
__global__ void k_count(const int* __restrict__ src,
                        const int* __restrict__ dst) {
    int e = blockIdx.x * blockDim.x + threadIdx.x;
    if (e < EE) {
        atomicAdd(&g_deg_out[src[e]], 1);
        atomicAdd(&g_deg_in[dst[e]], 1);
    }
}

__global__ void k_norms() {
    int i = blockIdx.x * blockDim.x + threadIdx.x;
    if (i < NN) {
        int d_o = g_deg_out[i];
        int d_i = g_deg_in[i];
        g_nsrc[i] = rsqrtf((float)(d_o > 0 ? d_o : 1));
        g_ndst[i] = rsqrtf((float)(d_i > 0 ? d_i : 1));
    }
}

__global__ void k_scan1() {
    __shared__ int sh[256];
    const int tid = threadIdx.x;
    const int base = blockIdx.x * 1024 + tid * 4;
    int v0 = (base + 0 < NN) ? g_deg_in[base + 0] : 0;
    int v1 = (base + 1 < NN) ? g_deg_in[base + 1] : 0;
    int v2 = (base + 2 < NN) ? g_deg_in[base + 2] : 0;
    int v3 = (base + 3 < NN) ? g_deg_in[base + 3] : 0;
    int p0 = v0, p1 = p0 + v1, p2 = p1 + v2, p3 = p2 + v3;
    sh[tid] = p3;
    __syncthreads();
    for (int off = 1; off < 256; off <<= 1) {
        int t = (tid >= off) ? sh[tid - off] : 0;
        __syncthreads();
        sh[tid] += t;
        __syncthreads();
    }
    int toff = sh[tid] - p3;
    if (base + 0 < NN) g_incl[base + 0] = toff + p0;
    if (base + 1 < NN) g_incl[base + 1] = toff + p1;
    if (base + 2 < NN) g_incl[base + 2] = toff + p2;
    if (base + 3 < NN) g_incl[base + 3] = toff + p3;
    if (tid == 0) g_bsums[blockIdx.x] = sh[255];
}

__global__ void k_scan2(int nb) {
    __shared__ int sh[128];
    const int tid = threadIdx.x;
    sh[tid] = (tid < nb) ? g_bsums[tid] : 0;
    __syncthreads();
    for (int off = 1; off < 128; off <<= 1) {
        int t = (tid >= off) ? sh[tid - off] : 0;
        __syncthreads();
        sh[tid] += t;
        __syncthreads();
    }
    if (tid < nb) g_bsums[tid] = sh[tid];
}

__global__ void k_scan3() {
    int i = blockIdx.x * blockDim.x + threadIdx.x;
    if (i < NN) {
        int blk = i >> 10;
        int off = (blk > 0) ? g_bsums[blk - 1] : 0;
        int excl = off + g_incl[i] - g_deg_in[i];
        g_rowptr[i] = excl;
        g_wptr[i] = excl;
    }
    if (i == 0) g_rowptr[NN] = EE;
}

__global__ void k_scatter(const int* __restrict__ src,
                          const int* __restrict__ dst) {
    int e = blockIdx.x * blockDim.x + threadIdx.x;
    if (e < EE) {
        int d = dst[e];
        int pos = atomicAdd(&g_wptr[d], 1);
        g_csr[pos] = src[e];
    }
}

// ---------------- tensor-core GEMM (bf16 HMMA): g_hA16 = A @ B --------------
// BM=128, BN=NC (128 or 64), BK=32. 256 threads = 8 warps (4 in M x 2 in N).
// mma.sync.m16n8k16.bf16, fp32 accumulate. Operands staged as bf16x2 pairs in
// a permuted [plane][lane] shared layout (stride 33 -> conflict-free LDS.32).

__device__ __forceinline__ void mma_bf16(float* d, const uint32_t* a, const uint32_t* b) {
    asm volatile(
        "mma.sync.aligned.m16n8k16.row.col.f32.bf16.bf16.f32 "
        "{%0,%1,%2,%3}, {%4,%5,%6,%7}, {%8,%9}, {%0,%1,%2,%3};"
        : "+f"(d[0]), "+f"(d[1]), "+f"(d[2]), "+f"(d[3])
        : "r"(a[0]), "r"(a[1]), "r"(a[2]), "r"(a[3]), "r"(b[0]), "r"(b[1]));
}

template<bool FROM_X, int BN>
__global__ __launch_bounds__(256)
void k_gemm_bf(const float* __restrict__ xext,
               const float* __restrict__ Bsrc,
               int M, int K) {
    const float* __restrict__ Af = xext;
    const __nv_bfloat16* __restrict__ Ah = (const __nv_bfloat16*)g_hB16;
    __nv_bfloat16* __restrict__ C = g_hA16;
    constexpr int NC = BN;
    constexpr int BK = 32;
    constexpr int APITER = (128 * (BK / 2)) / 256;   // 8 bf16x2 pairs / thread
    constexpr int BPITER = ((BK / 2) * BN) / 256;    // 8 (BN=128) or 4 (BN=64)
    constexpr int NT = BN / 16;                      // n-tiles per warp

    __shared__ uint32_t AsU[64 * 33];                      // [mt*2+ks][reg] planes
    __shared__ uint32_t BsU[(BN / 8) * 2 * 2 * 33];        // [nt*2+ks][reg] planes

    const int tid  = threadIdx.x;
    const int lane = tid & 31;
    const int w    = tid >> 5;
    const int warpM = w & 3;
    const int warpN = w >> 2;
    const int rowBase = blockIdx.x * 128;

    float acc[2][NT][4];
#pragma unroll
    for (int j = 0; j < 2; j++)
#pragma unroll
        for (int n = 0; n < NT; n++)
#pragma unroll
            for (int r = 0; r < 4; r++) acc[j][n][r] = 0.f;

    uint32_t sa[APITER];   // bf16x2 pairs (k even/odd)
    uint32_t sb[BPITER];

    auto loadAB = [&](int k0) {
#pragma unroll
        for (int i = 0; i < APITER; i++) {
            int pidx = i * 256 + tid;
            int m = pidx >> 4;                 // 16 pairs per row (BK=32)
            int kp = pidx & 15;
            int grow = rowBase + m;
            if (FROM_X) {
                float2 f = (grow < M) ? *(const float2*)&Af[(size_t)grow * K + k0 + kp * 2]
                                      : make_float2(0.f, 0.f);
                __nv_bfloat162 h = __float22bfloat162_rn(f);
                sa[i] = *(uint32_t*)&h;
            } else {
                sa[i] = (grow < M) ? *(const uint32_t*)&Ah[(size_t)grow * K + k0 + kp * 2]
                                   : 0u;
            }
        }
#pragma unroll
        for (int i = 0; i < BPITER; i++) {
            int idx = i * 256 + tid;
            int n = idx % BN;                  // n fastest (coalesced)
            int kp = idx / BN;                 // 0..15
            float w0 = Bsrc[(size_t)(k0 + kp * 2) * NC + n];
            float w1 = Bsrc[(size_t)(k0 + kp * 2 + 1) * NC + n];
            __nv_bfloat162 h = __float22bfloat162_rn(make_float2(w0, w1));
            sb[i] = *(uint32_t*)&h;
        }
    };

    auto storeAB = [&]() {
#pragma unroll
        for (int i = 0; i < APITER; i++) {
            int pidx = i * 256 + tid;
            int m = pidx >> 4;
            int kp = pidx & 15;
            int mt = m >> 4, rr = m & 15;
            int ks = kp >> 3, j = kp & 7;
            int ln = ((rr & 7) << 2) | (j & 3);
            int reg = (rr >> 3) | (((j >> 2) & 1) << 1);
            int plane = ((mt << 1) | ks) * 4 + reg;
            AsU[plane * 33 + ln] = sa[i];
        }
#pragma unroll
        for (int i = 0; i < BPITER; i++) {
            int idx = i * 256 + tid;
            int n = idx % BN;
            int kp = idx / BN;
            int nt = n >> 3, nn = n & 7;
            int ks = kp >> 3, jj = kp & 7;
            int ln = (nn << 2) | (jj & 3);
            int reg = jj >> 2;
            int plane = ((nt << 1) | ks) * 2 + reg;
            BsU[plane * 33 + ln] = sb[i];
        }
    };

    const int nChunks = K / BK;
    loadAB(0);
    storeAB();
    __syncthreads();

    for (int c = 0; c < nChunks; c++) {
        if (c + 1 < nChunks) loadAB((c + 1) * BK);

#pragma unroll
        for (int ks = 0; ks < 2; ks++) {
            uint32_t a[2][4];
#pragma unroll
            for (int j = 0; j < 2; j++) {
                int mt = warpM * 2 + j;
                int pb = ((mt << 1) | ks) * 4;
#pragma unroll
                for (int r = 0; r < 4; r++)
                    a[j][r] = AsU[(pb + r) * 33 + lane];
            }
#pragma unroll
            for (int n = 0; n < NT; n++) {
                int ntg = warpN * NT + n;
                int pb = ((ntg << 1) | ks) * 2;
                uint32_t b[2];
                b[0] = BsU[pb * 33 + lane];
                b[1] = BsU[(pb + 1) * 33 + lane];
                mma_bf16(acc[0][n], a[0], b);
                mma_bf16(acc[1][n], a[1], b);
            }
        }
        __syncthreads();
        if (c + 1 < nChunks) {
            storeAB();
            __syncthreads();
        }
    }

    // epilogue: m16n8 fp32 fragment -> bf16x2 stores
    const int r0 = rowBase + warpM * 32;
#pragma unroll
    for (int j = 0; j < 2; j++) {
        int row = r0 + j * 16 + (lane >> 2);
#pragma unroll
        for (int n = 0; n < NT; n++) {
            int col = warpN * (NT * 8) + n * 8 + (lane & 3) * 2;
            if (row < M) {
                __nv_bfloat162 o0 = __float22bfloat162_rn(make_float2(acc[j][n][0], acc[j][n][1]));
                *(uint32_t*)&C[(size_t)row * NC + col] = *(uint32_t*)&o0;
            }
            if (row + 8 < M) {
                __nv_bfloat162 o1 = __float22bfloat162_rn(make_float2(acc[j][n][2], acc[j][n][3]));
                *(uint32_t*)&C[(size_t)(row + 8) * NC + col] = *(uint32_t*)&o1;
            }
        }
    }
}

// ---------------- aggregation (bf16 in / bf16 out) --------------------------
// hB16[n] = bf16( n_dst[n] * sum_c(n_src[c] * hA16[c]) + b )
// One warp per node. uint4 per lane (8 bf16): 16 lanes cover a 128-feat row,
// so each warp load covers TWO edges (halves), 8 edges in flight per iter.
__global__ void k_agg128(const float* __restrict__ bias) {
    const __nv_bfloat16* __restrict__ hin = (const __nv_bfloat16*)g_hA16;
    __nv_bfloat16* __restrict__ hout = g_hB16;
    int gt = blockIdx.x * blockDim.x + threadIdx.x;
    int node = gt >> 5;
    int lane = gt & 31;
    if (node >= NN) return;
    int s0 = g_rowptr[node], s1 = g_rowptr[node + 1];
    const int half = lane >> 4;          // which edge of the pair
    const int fo = (lane & 15) * 8;      // 8 bf16 feats per lane

    float acc[4][8];
#pragma unroll
    for (int i = 0; i < 4; i++)
#pragma unroll
        for (int f = 0; f < 8; f++) acc[i][f] = 0.f;

    int e = s0;
    for (; e + 7 < s1; e += 8) {
#pragma unroll
        for (int i = 0; i < 4; i++) {
            int c = g_csr[e + 2 * i + half];
            float ns = g_nsrc[c];
            uint4 r = *(const uint4*)&hin[(size_t)c * 128 + fo];
            float2 f0 = __bfloat1622float2(*(__nv_bfloat162*)&r.x);
            float2 f1 = __bfloat1622float2(*(__nv_bfloat162*)&r.y);
            float2 f2 = __bfloat1622float2(*(__nv_bfloat162*)&r.z);
            float2 f3 = __bfloat1622float2(*(__nv_bfloat162*)&r.w);
            acc[i][0] += ns * f0.x; acc[i][1] += ns * f0.y;
            acc[i][2] += ns * f1.x; acc[i][3] += ns * f1.y;
            acc[i][4] += ns * f2.x; acc[i][5] += ns * f2.y;
            acc[i][6] += ns * f3.x; acc[i][7] += ns * f3.y;
        }
    }
    for (; e + 1 < s1; e += 2) {
        int c = g_csr[e + half];
        float ns = g_nsrc[c];
        uint4 r = *(const uint4*)&hin[(size_t)c * 128 + fo];
        float2 f0 = __bfloat1622float2(*(__nv_bfloat162*)&r.x);
        float2 f1 = __bfloat1622float2(*(__nv_bfloat162*)&r.y);
        float2 f2 = __bfloat1622float2(*(__nv_bfloat162*)&r.z);
        float2 f3 = __bfloat1622float2(*(__nv_bfloat162*)&r.w);
        acc[0][0] += ns * f0.x; acc[0][1] += ns * f0.y;
        acc[0][2] += ns * f1.x; acc[0][3] += ns * f1.y;
        acc[0][4] += ns * f2.x; acc[0][5] += ns * f2.y;
        acc[0][6] += ns * f3.x; acc[0][7] += ns * f3.y;
    }
    if (e < s1) {                         // single odd edge: half 1 contributes 0
        int c = g_csr[e];
        float ns = (half == 0) ? g_nsrc[c] : 0.f;
        uint4 r = *(const uint4*)&hin[(size_t)c * 128 + fo];
        float2 f0 = __bfloat1622float2(*(__nv_bfloat162*)&r.x);
        float2 f1 = __bfloat1622float2(*(__nv_bfloat162*)&r.y);
        float2 f2 = __bfloat1622float2(*(__nv_bfloat162*)&r.z);
        float2 f3 = __bfloat1622float2(*(__nv_bfloat162*)&r.w);
        acc[0][0] += ns * f0.x; acc[0][1] += ns * f0.y;
        acc[0][2] += ns * f1.x; acc[0][3] += ns * f1.y;
        acc[0][4] += ns * f2.x; acc[0][5] += ns * f2.y;
        acc[0][6] += ns * f3.x; acc[0][7] += ns * f3.y;
    }

    float tot[8];
#pragma unroll
    for (int f = 0; f < 8; f++) {
        tot[f] = (acc[0][f] + acc[1][f]) + (acc[2][f] + acc[3][f]);
        tot[f] += __shfl_xor_sync(0xFFFFFFFFu, tot[f], 16);
    }

    if (half == 0) {
        float nd = g_ndst[node];
        float4 b0 = *(const float4*)&bias[fo];
        float4 b1 = *(const float4*)&bias[fo + 4];
        __nv_bfloat162 p0 = __float22bfloat162_rn(make_float2(tot[0] * nd + b0.x, tot[1] * nd + b0.y));
        __nv_bfloat162 p1 = __float22bfloat162_rn(make_float2(tot[2] * nd + b0.z, tot[3] * nd + b0.w));
        __nv_bfloat162 p2 = __float22bfloat162_rn(make_float2(tot[4] * nd + b1.x, tot[5] * nd + b1.y));
        __nv_bfloat162 p3 = __float22bfloat162_rn(make_float2(tot[6] * nd + b1.z, tot[7] * nd + b1.w));
        uint4 o;
        o.x = *(uint32_t*)&p0; o.y = *(uint32_t*)&p1;
        o.z = *(uint32_t*)&p2; o.w = *(uint32_t*)&p3;
        *(uint4*)&hout[(size_t)node * 128 + fo] = o;
    }
}

// Final layer: 64 bf16 feats = 128 B/row; 8 lanes per edge -> 4 edges/instr.
__global__ void k_agg64_softmax(float* __restrict__ out,
                                const float* __restrict__ bias) {
    const __nv_bfloat16* __restrict__ hin = (const __nv_bfloat16*)g_hA16;
    int gt = blockIdx.x * blockDim.x + threadIdx.x;
    int node = gt >> 5;
    int lane = gt & 31;
    if (node >= NN) return;
    int s0 = g_rowptr[node], s1 = g_rowptr[node + 1];
    const int quarter = lane >> 3;        // which edge of the quad
    const int fo = (lane & 7) * 8;        // 8 bf16 feats per lane

    float acc[2][8];
#pragma unroll
    for (int i = 0; i < 2; i++)
#pragma unroll
        for (int f = 0; f < 8; f++) acc[i][f] = 0.f;

    int e = s0;
    for (; e + 7 < s1; e += 8) {
#pragma unroll
        for (int i = 0; i < 2; i++) {
            int c = g_csr[e + 4 * i + quarter];
            float ns = g_nsrc[c];
            uint4 r = *(const uint4*)&hin[(size_t)c * 64 + fo];
            float2 f0 = __bfloat1622float2(*(__nv_bfloat162*)&r.x);
            float2 f1 = __bfloat1622float2(*(__nv_bfloat162*)&r.y);
            float2 f2 = __bfloat1622float2(*(__nv_bfloat162*)&r.z);
            float2 f3 = __bfloat1622float2(*(__nv_bfloat162*)&r.w);
            acc[i][0] += ns * f0.x; acc[i][1] += ns * f0.y;
            acc[i][2] += ns * f1.x; acc[i][3] += ns * f1.y;
            acc[i][4] += ns * f2.x; acc[i][5] += ns * f2.y;
            acc[i][6] += ns * f3.x; acc[i][7] += ns * f3.y;
        }
    }
    for (; e + 3 < s1; e += 4) {
        int c = g_csr[e + quarter];
        float ns = g_nsrc[c];
        uint4 r = *(const uint4*)&hin[(size_t)c * 64 + fo];
        float2 f0 = __bfloat1622float2(*(__nv_bfloat162*)&r.x);
        float2 f1 = __bfloat1622float2(*(__nv_bfloat162*)&r.y);
        float2 f2 = __bfloat1622float2(*(__nv_bfloat162*)&r.z);
        float2 f3 = __bfloat1622float2(*(__nv_bfloat162*)&r.w);
        acc[0][0] += ns * f0.x; acc[0][1] += ns * f0.y;
        acc[0][2] += ns * f1.x; acc[0][3] += ns * f1.y;
        acc[0][4] += ns * f2.x; acc[0][5] += ns * f2.y;
        acc[0][6] += ns * f3.x; acc[0][7] += ns * f3.y;
    }
    if (e < s1) {                          // 1..3 remaining edges
        int rem = s1 - e;
        int c = g_csr[e + (quarter < rem ? quarter : 0)];
        float ns = (quarter < rem) ? g_nsrc[c] : 0.f;
        uint4 r = *(const uint4*)&hin[(size_t)c * 64 + fo];
        float2 f0 = __bfloat1622float2(*(__nv_bfloat162*)&r.x);
        float2 f1 = __bfloat1622float2(*(__nv_bfloat162*)&r.y);
        float2 f2 = __bfloat1622float2(*(__nv_bfloat162*)&r.z);
        float2 f3 = __bfloat1622float2(*(__nv_bfloat162*)&r.w);
        acc[0][0] += ns * f0.x; acc[0][1] += ns * f0.y;
        acc[0][2] += ns * f1.x; acc[0][3] += ns * f1.y;
        acc[0][4] += ns * f2.x; acc[0][5] += ns * f2.y;
        acc[0][6] += ns * f3.x; acc[0][7] += ns * f3.y;
    }

    float v[8];
    float nd = g_ndst[node];
#pragma unroll
    for (int f = 0; f < 8; f++) {
        float t = acc[0][f] + acc[1][f];
        t += __shfl_xor_sync(0xFFFFFFFFu, t, 8);
        t += __shfl_xor_sync(0xFFFFFFFFu, t, 16);
        v[f] = t * nd + bias[fo + f];
    }

    // softmax over 64 vals = 8 lanes (lane&7 groups) x 8 local
    float m = v[0];
#pragma unroll
    for (int f = 1; f < 8; f++) m = fmaxf(m, v[f]);
#pragma unroll
    for (int off = 4; off > 0; off >>= 1)
        m = fmaxf(m, __shfl_xor_sync(0xFFFFFFFFu, m, off));
    float s = 0.f;
    float ev[8];
#pragma unroll
    for (int f = 0; f < 8; f++) { ev[f] = __expf(v[f] - m); s += ev[f]; }
#pragma unroll
    for (int off = 4; off > 0; off >>= 1)
        s += __shfl_xor_sync(0xFFFFFFFFu, s, off);
    float inv = 1.0f / s;

    if (quarter == 0) {                    // lanes 0..7 write 8 fp32 each
        float4 o0 = make_float4(ev[0] * inv, ev[1] * inv, ev[2] * inv, ev[3] * inv);
        float4 o1 = make_float4(ev[4] * inv, ev[5] * inv, ev[6] * inv, ev[7] * inv);
        *(float4*)&out[(size_t)node * 64 + fo] = o0;
        *(float4*)&out[(size_t)node * 64 + fo + 4] = o1;
    }
}

// ---------------- launch -----------------------------------------------------
extern "C" void kernel_launch(void* const* d_in, const int* in_sizes, int n_in,
                              void* d_out, int out_size) {
    const float* x   = (const float*)d_in[0];
    const int*   src = (const int*)d_in[1];    // int32: JAX x64 disabled
    const int*   dst = (const int*)d_in[2];
    const float* W0  = (const float*)d_in[3];
    const float* b0  = (const float*)d_in[4];
    const float* W1  = (const float*)d_in[5];
    const float* b1  = (const float*)d_in[6];
    const float* W2  = (const float*)d_in[7];
    const float* b2  = (const float*)d_in[8];
    float* out = (float*)d_out;

    const int nblk = (NN + 255) / 256;
    const int eblk = (EE + 255) / 256;
    const int sblk = (NN + 1023) / 1024;   // 98

    // graph preprocessing
    k_zero_deg<<<nblk, 256>>>();
    k_count<<<eblk, 256>>>(src, dst);
    k_norms<<<nblk, 256>>>();
    k_scan1<<<sblk, 256>>>();
    k_scan2<<<1, 128>>>(sblk);
    k_scan3<<<nblk, 256>>>();
    k_scatter<<<eblk, 256>>>(src, dst);

    const int aggblk  = (NN * 32 + 255) / 256;   // 12500
    const int gemmblk = (NN + 127) / 128;        // 782

    // layer 0: x @ W0 -> hA16 ; aggregate -> hB16
    k_gemm_bf<true, HID><<<gemmblk, 256>>>(x, W0, NN, F0);
    k_agg128<<<aggblk, 256>>>(b0);
    // layer 1: hB16 @ W1 -> hA16 ; aggregate -> hB16
    k_gemm_bf<false, HID><<<gemmblk, 256>>>(nullptr, W1, NN, HID);
    k_agg128<<<aggblk, 256>>>(b1);
    // layer 2: hB16 @ W2 -> hA16 ; aggregate + softmax -> out
    k_gemm_bf<false, NCLS><<<gemmblk, 256>>>(nullptr, W2, NN, HID);
    k_agg64_softmax<<<aggblk, 256>>>(out, b2);
}